// round 3
// baseline (speedup 1.0000x reference)
#include <cuda_runtime.h>
#include <cuda_fp16.h>
#include <mma.h>
#include <cstddef>

using namespace nvcuda;

#define NN 100000
#define NE 1600000

// Scratch (allocation-free rule: __device__ globals)
__device__ float  g_acc[(size_t)NN * 128];   // segment sums  [N,128]
__device__ float  g_cnt[NN];                 // segment counts
__device__ __half g_mid[(size_t)NN * 256];   // node MLP hidden [N,256] fp16
__device__ int    g_is64;                    // edge_index dtype flag

// ---------------------------------------------------------------------------
// K-1: detect edge_index dtype (int64 vs int32)
// ---------------------------------------------------------------------------
__global__ void detect_kernel(const long long* __restrict__ ei)
{
    if (threadIdx.x == 0 && blockIdx.x == 0) {
        int ok = 1;
        for (int i = 0; i < 128; i++) {
            long long v = ei[i];
            if (v < 0 || v >= NN) { ok = 0; break; }
        }
        g_is64 = ok;
    }
}

// ---------------------------------------------------------------------------
// K0: zero accumulators
// ---------------------------------------------------------------------------
__global__ void zero_kernel()
{
    size_t i = (size_t)blockIdx.x * blockDim.x + threadIdx.x;
    size_t stride = (size_t)gridDim.x * blockDim.x;
    for (size_t k = i; k < (size_t)NN * 128; k += stride) g_acc[k] = 0.0f;
    for (size_t k = i; k < (size_t)NN; k += stride) g_cnt[k] = 0.0f;
}

// ---------------------------------------------------------------------------
// K1: edge MLP (tensor cores) + scatter-add
//   A[128x48] = [x[src] | edge_attr | 0pad]
//   h1 = relu(A @ W1 + b1)   (48->64, rows 43..47 of W1 zero)
//   h2 = relu(h1 @ W2 + b2)  (64->128)
//   g_acc[dst] += h2 ; g_cnt[dst] += 1
// Dynamic smem layout (bytes):
//   sA   @ 0      : 128*48 half  = 12288
//   sW1  @ 12288  : 48*64  half  =  6144
//   sH   @ 18432  : 128*72 half  = 18432   (ld 72)
//   sW2  @ 36864  : 64*128 half  = 16384
//   oF   @ 53248  : 128*128 f32  = 65536   -> total 118784
// ---------------------------------------------------------------------------
#define EDGE_SMEM 118784

__global__ __launch_bounds__(256)
void edge_kernel(const float* __restrict__ x,
                 const void* __restrict__ ei_raw,
                 const float* __restrict__ ea,
                 const float* __restrict__ W1, const float* __restrict__ b1,
                 const float* __restrict__ W2, const float* __restrict__ b2)
{
    extern __shared__ __align__(16) char smem[];
    __half* sA  = (__half*)(smem);
    __half* sW1 = (__half*)(smem + 12288);
    __half* sH  = (__half*)(smem + 18432);
    __half* sW2 = (__half*)(smem + 36864);
    float*  oF  = (float*)(smem + 53248);

    __shared__ int   sDst[128], sSrc[128];
    __shared__ float sb1s[64], sb2s[128];

    const int t  = threadIdx.x;
    const int e0 = blockIdx.x * 128;   // NE = 12500*128 exactly

    if (t < 128) {
        int e = e0 + t, d, s;
        if (g_is64) {
            const long long* ei = (const long long*)ei_raw;
            d = (int)ei[e]; s = (int)ei[NE + e];
        } else {
            const int* ei = (const int*)ei_raw;
            d = ei[e]; s = ei[NE + e];
        }
        sDst[t] = min(max(d, 0), NN - 1);
        sSrc[t] = min(max(s, 0), NN - 1);
    }
    if (t < 64) sb1s[t] = b1[t];
    if (t >= 128) sb2s[t - 128] = b2[t - 128];

    for (int i = t; i < 48 * 64; i += 256) {
        int k = i >> 6;
        sW1[i] = (k < 43) ? __float2half_rn(W1[i]) : __half(0.0f);
    }
    for (int i = t; i < 64 * 128; i += 256) sW2[i] = __float2half_rn(W2[i]);
    __syncthreads();

    // Fill A
    for (int i = t; i < 128 * 48; i += 256) {
        int r = i / 48, c = i - r * 48;
        float v;
        if (c < 4)       v = x[(size_t)sSrc[r] * 4 + c];
        else if (c < 43) v = ea[(size_t)(e0 + r) * 39 + (c - 4)];
        else             v = 0.0f;
        sA[i] = __float2half_rn(v);
    }
    __syncthreads();

    const int w = t >> 5;   // warp id, 0..7 ; warp owns M-tile w

    // GEMM1: [128x48] @ [48x64] -> oF (ld 64)
    for (int nt = 0; nt < 4; nt++) {
        wmma::fragment<wmma::accumulator, 16, 16, 16, float> c;
        wmma::fill_fragment(c, 0.0f);
        for (int kt = 0; kt < 3; kt++) {
            wmma::fragment<wmma::matrix_a, 16, 16, 16, __half, wmma::row_major> a;
            wmma::fragment<wmma::matrix_b, 16, 16, 16, __half, wmma::row_major> b;
            wmma::load_matrix_sync(a, sA + w * 16 * 48 + kt * 16, 48);
            wmma::load_matrix_sync(b, sW1 + kt * 16 * 64 + nt * 16, 64);
            wmma::mma_sync(c, a, b, c);
        }
        wmma::store_matrix_sync(oF + w * 16 * 64 + nt * 16, c, 64, wmma::mem_row_major);
    }
    __syncthreads();

    // bias + relu -> sH fp16 (ld 72)
    for (int i = t; i < 128 * 64; i += 256) {
        int r = i >> 6, c = i & 63;
        sH[r * 72 + c] = __float2half_rn(fmaxf(oF[i] + sb1s[c], 0.0f));
    }
    __syncthreads();

    // GEMM2: [128x64] @ [64x128] -> oF (ld 128)
    for (int nt = 0; nt < 8; nt++) {
        wmma::fragment<wmma::accumulator, 16, 16, 16, float> c;
        wmma::fill_fragment(c, 0.0f);
        for (int kt = 0; kt < 4; kt++) {
            wmma::fragment<wmma::matrix_a, 16, 16, 16, __half, wmma::row_major> a;
            wmma::fragment<wmma::matrix_b, 16, 16, 16, __half, wmma::row_major> b;
            wmma::load_matrix_sync(a, sH + w * 16 * 72 + kt * 16, 72);
            wmma::load_matrix_sync(b, sW2 + kt * 16 * 128 + nt * 16, 128);
            wmma::mma_sync(c, a, b, c);
        }
        wmma::store_matrix_sync(oF + w * 16 * 128 + nt * 16, c, 128, wmma::mem_row_major);
    }
    __syncthreads();

    // bias + relu + float4 atomic scatter
    {
        int r = t >> 1, hf = t & 1;
        int dst = sDst[r];
        float* ab = g_acc + (size_t)dst * 128 + hf * 64;
        const float* of = oF + r * 128 + hf * 64;
        const float* bb = sb2s + hf * 64;
#pragma unroll
        for (int j = 0; j < 16; j++) {
            float4 v = make_float4(fmaxf(of[4 * j + 0] + bb[4 * j + 0], 0.0f),
                                   fmaxf(of[4 * j + 1] + bb[4 * j + 1], 0.0f),
                                   fmaxf(of[4 * j + 2] + bb[4 * j + 2], 0.0f),
                                   fmaxf(of[4 * j + 3] + bb[4 * j + 3], 0.0f));
            atomicAdd(reinterpret_cast<float4*>(ab + 4 * j), v);
        }
        if (hf == 0) atomicAdd(&g_cnt[dst], 1.0f);
    }
}

// ---------------------------------------------------------------------------
// K2: node MLP layer 1 (tensor cores)
//   in = [x[n] | g_acc[n]/max(cnt,1) | 0pad]  (144)
//   g_mid[n] = relu(in @ W3 + b3)             (->256, fp16)
// smem: sIn @0 (128*144 half =36864), sW @36864 (144*128 half =36864),
//       oF @73728 (128*128 f32 =65536) -> 139264
// ---------------------------------------------------------------------------
#define NODE1_SMEM 139264

__global__ __launch_bounds__(256)
void node1_kernel(const float* __restrict__ x,
                  const float* __restrict__ W3, const float* __restrict__ b3)
{
    extern __shared__ __align__(16) char smem[];
    __half* sIn = (__half*)(smem);
    __half* sW  = (__half*)(smem + 36864);
    float*  oF  = (float*)(smem + 73728);

    __shared__ float sInv[128];
    __shared__ float sb[128];

    const int t  = threadIdx.x;
    const int n0 = blockIdx.x * 128;

    if (t < 128) {
        int nd = min(n0 + t, NN - 1);
        sInv[t] = 1.0f / fmaxf(g_cnt[nd], 1.0f);
    }
    __syncthreads();

    for (int i = t; i < 128 * 144; i += 256) {
        int r = i / 144, c = i - r * 144;
        int nd = min(n0 + r, NN - 1);
        float v;
        if (c < 4)        v = x[(size_t)nd * 4 + c];
        else if (c < 132) v = g_acc[(size_t)nd * 128 + (c - 4)] * sInv[r];
        else              v = 0.0f;
        sIn[i] = __float2half_rn(v);
    }

    const int w = t >> 5;

#pragma unroll 1
    for (int nc = 0; nc < 2; nc++) {
        if (nc) __syncthreads();    // protect previous chunk's sW/oF
        for (int i = t; i < 144 * 128; i += 256) {
            int k = i >> 7, j = i & 127;
            sW[i] = (k < 132) ? __float2half_rn(W3[k * 256 + nc * 128 + j])
                              : __half(0.0f);
        }
        if (t < 128) sb[t] = b3[nc * 128 + t];
        __syncthreads();

        for (int nt = 0; nt < 8; nt++) {
            wmma::fragment<wmma::accumulator, 16, 16, 16, float> c;
            wmma::fill_fragment(c, 0.0f);
            for (int kt = 0; kt < 9; kt++) {
                wmma::fragment<wmma::matrix_a, 16, 16, 16, __half, wmma::row_major> a;
                wmma::fragment<wmma::matrix_b, 16, 16, 16, __half, wmma::row_major> b;
                wmma::load_matrix_sync(a, sIn + w * 16 * 144 + kt * 16, 144);
                wmma::load_matrix_sync(b, sW + kt * 16 * 128 + nt * 16, 128);
                wmma::mma_sync(c, a, b, c);
            }
            wmma::store_matrix_sync(oF + w * 16 * 128 + nt * 16, c, 128, wmma::mem_row_major);
        }
        __syncthreads();

        for (int i = t; i < 128 * 128; i += 256) {
            int r = i >> 7, c = i & 127;
            int node = n0 + r;
            if (node < NN)
                g_mid[(size_t)node * 256 + nc * 128 + c] =
                    __float2half_rn(fmaxf(oF[i] + sb[c], 0.0f));
        }
    }
}

// ---------------------------------------------------------------------------
// K3: node MLP layer 2 (tensor cores): out = relu(g_mid @ W4 + b4)
// smem: sIn @0 (128*264 half =67584), sW @67584 (256*128 half =65536),
//       oF @133120 (65536) -> 198656
// ---------------------------------------------------------------------------
#define NODE2_SMEM 198656

__global__ __launch_bounds__(256)
void node2_kernel(const float* __restrict__ W4, const float* __restrict__ b4,
                  float* __restrict__ out)
{
    extern __shared__ __align__(16) char smem[];
    __half* sIn = (__half*)(smem);            // ld 264
    __half* sW  = (__half*)(smem + 67584);
    float*  oF  = (float*)(smem + 133120);

    __shared__ float sb[128];

    const int t  = threadIdx.x;
    const int n0 = blockIdx.x * 128;

    for (int i = t; i < 128 * 256; i += 256) {
        int r = i >> 8, c = i & 255;
        int nd = min(n0 + r, NN - 1);
        sIn[r * 264 + c] = g_mid[(size_t)nd * 256 + c];
    }

    const int w = t >> 5;

#pragma unroll 1
    for (int nc = 0; nc < 2; nc++) {
        if (nc) __syncthreads();
        for (int i = t; i < 256 * 128; i += 256) {
            int k = i >> 7, j = i & 127;
            sW[i] = __float2half_rn(W4[k * 256 + nc * 128 + j]);
        }
        if (t < 128) sb[t] = b4[nc * 128 + t];
        __syncthreads();

        for (int nt = 0; nt < 8; nt++) {
            wmma::fragment<wmma::accumulator, 16, 16, 16, float> c;
            wmma::fill_fragment(c, 0.0f);
            for (int kt = 0; kt < 16; kt++) {
                wmma::fragment<wmma::matrix_a, 16, 16, 16, __half, wmma::row_major> a;
                wmma::fragment<wmma::matrix_b, 16, 16, 16, __half, wmma::row_major> b;
                wmma::load_matrix_sync(a, sIn + w * 16 * 264 + kt * 16, 264);
                wmma::load_matrix_sync(b, sW + kt * 16 * 128 + nt * 16, 128);
                wmma::mma_sync(c, a, b, c);
            }
            wmma::store_matrix_sync(oF + w * 16 * 128 + nt * 16, c, 128, wmma::mem_row_major);
        }
        __syncthreads();

        for (int i = t; i < 128 * 128; i += 256) {
            int r = i >> 7, c = i & 127;
            int node = n0 + r;
            if (node < NN)
                out[(size_t)node * 256 + nc * 128 + c] = fmaxf(oF[i] + sb[c], 0.0f);
        }
    }
}

// ---------------------------------------------------------------------------
// launch
// ---------------------------------------------------------------------------
extern "C" void kernel_launch(void* const* d_in, const int* in_sizes, int n_in,
                              void* d_out, int out_size)
{
    const float* x  = (const float*)d_in[0];
    const void*  ei = d_in[1];
    const float* ea = (const float*)d_in[2];
    const float* W1 = (const float*)d_in[3];
    const float* b1 = (const float*)d_in[4];
    const float* W2 = (const float*)d_in[5];
    const float* b2 = (const float*)d_in[6];
    const float* W3 = (const float*)d_in[7];
    const float* b3 = (const float*)d_in[8];
    const float* W4 = (const float*)d_in[9];
    const float* b4 = (const float*)d_in[10];
    float* out = (float*)d_out;

    cudaFuncSetAttribute(edge_kernel,
                         cudaFuncAttributeMaxDynamicSharedMemorySize, EDGE_SMEM);
    cudaFuncSetAttribute(node1_kernel,
                         cudaFuncAttributeMaxDynamicSharedMemorySize, NODE1_SMEM);
    cudaFuncSetAttribute(node2_kernel,
                         cudaFuncAttributeMaxDynamicSharedMemorySize, NODE2_SMEM);

    detect_kernel<<<1, 32>>>((const long long*)ei);
    zero_kernel<<<2048, 256>>>();
    edge_kernel<<<NE / 128, 256, EDGE_SMEM>>>(x, ei, ea, W1, b1, W2, b2);
    node1_kernel<<<(NN + 127) / 128, 256, NODE1_SMEM>>>(x, W3, b3);
    node2_kernel<<<(NN + 127) / 128, 256, NODE2_SMEM>>>(W4, b4, out);
}

// round 4
// speedup vs baseline: 2.6009x; 2.6009x over previous
#include <cuda_runtime.h>
#include <cuda_fp16.h>
#include <mma.h>
#include <cstddef>

using namespace nvcuda;

#define NN 100000
#define NE 1600000

// Scratch (allocation-free rule: __device__ globals)
__device__ float  g_acc[(size_t)NN * 128];   // segment sums  [N,128]
__device__ float  g_cnt[NN];                 // segment counts
__device__ __half g_mid[(size_t)NN * 256];   // node MLP hidden [N,256] fp16
__device__ int    g_is64;                    // edge_index dtype flag

// ---------------------------------------------------------------------------
// K-1: detect edge_index dtype (int64 vs int32)
// ---------------------------------------------------------------------------
__global__ void detect_kernel(const long long* __restrict__ ei)
{
    if (threadIdx.x == 0 && blockIdx.x == 0) {
        int ok = 1;
        for (int i = 0; i < 128; i++) {
            long long v = ei[i];
            if (v < 0 || v >= NN) { ok = 0; break; }
        }
        g_is64 = ok;
    }
}

// ---------------------------------------------------------------------------
// K0: zero accumulators
// ---------------------------------------------------------------------------
__global__ void zero_kernel()
{
    size_t i = (size_t)blockIdx.x * blockDim.x + threadIdx.x;
    size_t stride = (size_t)gridDim.x * blockDim.x;
    for (size_t k = i; k < (size_t)NN * 128; k += stride) g_acc[k] = 0.0f;
    for (size_t k = i; k < (size_t)NN; k += stride) g_cnt[k] = 0.0f;
}

// ---------------------------------------------------------------------------
// K1: edge MLP (wmma) + scatter
//   A[128x48]=[x[src]|ea|0], h1=relu(A@W1+b1) (48->64), h2=relu(h1@W2+b2)
//   (64->128), g_acc[dst]+=h2, g_cnt[dst]+=1
// smem (halves, padded ld): sA 128x56 @0 (14336B), sW1 48x72 @14336 (6912B),
//   sH 128x72 @21248 (18432B), sW2 64x136 @39680 (17408B),
//   wbuf 8x(16x16 f32) @57088 (8192B) -> 65280B => 3 CTAs/SM
// ---------------------------------------------------------------------------
#define E_SA   0
#define E_SW1  14336
#define E_SH   21248
#define E_SW2  39680
#define E_WBUF 57088
#define EDGE_SMEM 65280

__global__ __launch_bounds__(256, 3)
void edge_kernel(const float* __restrict__ x,
                 const void* __restrict__ ei_raw,
                 const float* __restrict__ ea,
                 const float* __restrict__ W1, const float* __restrict__ b1,
                 const float* __restrict__ W2, const float* __restrict__ b2)
{
    extern __shared__ __align__(128) char smem[];
    __half* sA  = (__half*)(smem + E_SA);    // ld 56
    __half* sW1 = (__half*)(smem + E_SW1);   // ld 72
    __half* sH  = (__half*)(smem + E_SH);    // ld 72
    __half* sW2 = (__half*)(smem + E_SW2);   // ld 136
    float*  wbuf = (float*)(smem + E_WBUF);

    __shared__ int   sDst[128], sSrc[128];
    __shared__ float sb1s[64], sb2s[128];

    const int t = threadIdx.x;
    const int w = t >> 5, lane = t & 31;
    const int e0 = blockIdx.x * 128;          // NE = 12500*128 exactly
    float* wb = wbuf + w * 256;

    if (t < 128) {
        int e = e0 + t, d, s;
        if (g_is64) {
            const long long* ei = (const long long*)ei_raw;
            d = (int)ei[e]; s = (int)ei[NE + e];
        } else {
            const int* ei = (const int*)ei_raw;
            d = ei[e]; s = ei[NE + e];
        }
        sDst[t] = min(max(d, 0), NN - 1);
        sSrc[t] = min(max(s, 0), NN - 1);
    }
    if (t < 64) sb1s[t] = b1[t];
    if (t >= 128) sb2s[t - 128] = b2[t - 128];

    for (int i = t; i < 48 * 72; i += 256) {
        int k = i / 72, j = i - k * 72;
        sW1[i] = (k < 43 && j < 64) ? __float2half_rn(W1[k * 64 + j]) : __half(0.0f);
    }
    for (int i = t; i < 64 * 136; i += 256) {
        int k = i / 136, j = i - k * 136;
        sW2[i] = (j < 128) ? __float2half_rn(W2[k * 128 + j]) : __half(0.0f);
    }
    __syncthreads();   // sSrc ready

    for (int i = t; i < 128 * 48; i += 256) {
        int r = i / 48, c = i - r * 48;
        float v;
        if (c < 4)       v = x[(size_t)sSrc[r] * 4 + c];
        else if (c < 43) v = ea[(size_t)(e0 + r) * 39 + (c - 4)];
        else             v = 0.0f;
        sA[r * 56 + c] = __float2half_rn(v);
    }
    __syncthreads();

    const int rr = lane >> 1, cb = (lane & 1) * 8;   // epilogue mapping

    // --- GEMM1: warp w rows [16w,16w+16), K=48, N=64, 4 accumulators ---
    {
        wmma::fragment<wmma::accumulator, 16, 16, 16, float> c1[4];
#pragma unroll
        for (int nt = 0; nt < 4; nt++) wmma::fill_fragment(c1[nt], 0.0f);
#pragma unroll
        for (int kt = 0; kt < 3; kt++) {
            wmma::fragment<wmma::matrix_a, 16, 16, 16, __half, wmma::row_major> a;
            wmma::load_matrix_sync(a, sA + w * 16 * 56 + kt * 16, 56);
#pragma unroll
            for (int nt = 0; nt < 4; nt++) {
                wmma::fragment<wmma::matrix_b, 16, 16, 16, __half, wmma::row_major> b;
                wmma::load_matrix_sync(b, sW1 + kt * 16 * 72 + nt * 16, 72);
                wmma::mma_sync(c1[nt], a, b, c1[nt]);
            }
        }
#pragma unroll
        for (int nt = 0; nt < 4; nt++) {
            wmma::store_matrix_sync(wb, c1[nt], 16, wmma::mem_row_major);
            __syncwarp();
#pragma unroll
            for (int c = 0; c < 8; c++) {
                float v = wb[rr * 16 + cb + c] + sb1s[nt * 16 + cb + c];
                sH[(w * 16 + rr) * 72 + nt * 16 + cb + c] =
                    __float2half_rn(fmaxf(v, 0.0f));
            }
            __syncwarp();
        }
    }
    __syncthreads();

    // --- GEMM2: K=64, N=128 in 2 halves of 64, bias+relu+atomic scatter ---
#pragma unroll 1
    for (int nh = 0; nh < 2; nh++) {
        wmma::fragment<wmma::accumulator, 16, 16, 16, float> c2[4];
#pragma unroll
        for (int nt = 0; nt < 4; nt++) wmma::fill_fragment(c2[nt], 0.0f);
#pragma unroll
        for (int kt = 0; kt < 4; kt++) {
            wmma::fragment<wmma::matrix_a, 16, 16, 16, __half, wmma::row_major> a;
            wmma::load_matrix_sync(a, sH + w * 16 * 72 + kt * 16, 72);
#pragma unroll
            for (int nt = 0; nt < 4; nt++) {
                wmma::fragment<wmma::matrix_b, 16, 16, 16, __half, wmma::row_major> b;
                wmma::load_matrix_sync(b, sW2 + kt * 16 * 136 + nh * 64 + nt * 16, 136);
                wmma::mma_sync(c2[nt], a, b, c2[nt]);
            }
        }
#pragma unroll
        for (int nt = 0; nt < 4; nt++) {
            wmma::store_matrix_sync(wb, c2[nt], 16, wmma::mem_row_major);
            __syncwarp();
            const int colb = nh * 64 + nt * 16 + cb;
            const int dst = sDst[w * 16 + rr];
            float* ab = g_acc + (size_t)dst * 128 + colb;
            const float* wr = wb + rr * 16 + cb;
            const float* bb = sb2s + colb;
            float4 v0 = make_float4(fmaxf(wr[0] + bb[0], 0.0f),
                                    fmaxf(wr[1] + bb[1], 0.0f),
                                    fmaxf(wr[2] + bb[2], 0.0f),
                                    fmaxf(wr[3] + bb[3], 0.0f));
            float4 v1 = make_float4(fmaxf(wr[4] + bb[4], 0.0f),
                                    fmaxf(wr[5] + bb[5], 0.0f),
                                    fmaxf(wr[6] + bb[6], 0.0f),
                                    fmaxf(wr[7] + bb[7], 0.0f));
            atomicAdd(reinterpret_cast<float4*>(ab), v0);
            atomicAdd(reinterpret_cast<float4*>(ab + 4), v1);
            __syncwarp();
        }
    }
    if (t < 128) atomicAdd(&g_cnt[sDst[t]], 1.0f);
}

// ---------------------------------------------------------------------------
// K2: node MLP layer 1: in=[x|mean|0] (144), out=relu(in@W3+b3) -> g_mid fp16
// smem: sIn 128x152 @0 (38912B), sW 144x136 @38912 (39168B),
//       wbuf @78080 (8192B) -> 86272B => 2 CTAs/SM
// ---------------------------------------------------------------------------
#define N1_SIN  0
#define N1_SW   38912
#define N1_WBUF 78080
#define NODE1_SMEM 86272

__global__ __launch_bounds__(256, 2)
void node1_kernel(const float* __restrict__ x,
                  const float* __restrict__ W3, const float* __restrict__ b3)
{
    extern __shared__ __align__(128) char smem[];
    __half* sIn = (__half*)(smem + N1_SIN);  // ld 152
    __half* sW  = (__half*)(smem + N1_SW);   // ld 136
    float*  wbuf = (float*)(smem + N1_WBUF);

    __shared__ float sInv[128];
    __shared__ float sb[128];

    const int t = threadIdx.x;
    const int w = t >> 5, lane = t & 31;
    const int n0 = blockIdx.x * 128;
    float* wb = wbuf + w * 256;

    if (t < 128) {
        int nd = min(n0 + t, NN - 1);
        sInv[t] = 1.0f / fmaxf(g_cnt[nd], 1.0f);
    }
    __syncthreads();

    for (int i = t; i < 128 * 144; i += 256) {
        int r = i / 144, c = i - r * 144;
        int nd = min(n0 + r, NN - 1);
        float v = (c < 4) ? x[(size_t)nd * 4 + c]
                          : g_acc[(size_t)nd * 128 + (c - 4)] * sInv[r];
        sIn[r * 152 + c] = __float2half_rn(v);
    }

    const int rr = lane >> 1, cb = (lane & 1) * 8;

#pragma unroll 1
    for (int nc = 0; nc < 2; nc++) {
        __syncthreads();   // sIn ready (nc=0) / previous chunk done (nc=1)
        for (int i = t; i < 144 * 128; i += 256) {
            int k = i >> 7, j = i & 127;
            sW[k * 136 + j] = (k < 132) ? __float2half_rn(W3[k * 256 + nc * 128 + j])
                                        : __half(0.0f);
        }
        if (t < 128) sb[t] = b3[nc * 128 + t];
        __syncthreads();

#pragma unroll 1
        for (int nh = 0; nh < 2; nh++) {
            wmma::fragment<wmma::accumulator, 16, 16, 16, float> acc[4];
#pragma unroll
            for (int nt = 0; nt < 4; nt++) wmma::fill_fragment(acc[nt], 0.0f);
#pragma unroll
            for (int kt = 0; kt < 9; kt++) {
                wmma::fragment<wmma::matrix_a, 16, 16, 16, __half, wmma::row_major> a;
                wmma::load_matrix_sync(a, sIn + w * 16 * 152 + kt * 16, 152);
#pragma unroll
                for (int nt = 0; nt < 4; nt++) {
                    wmma::fragment<wmma::matrix_b, 16, 16, 16, __half, wmma::row_major> b;
                    wmma::load_matrix_sync(b, sW + kt * 16 * 136 + nh * 64 + nt * 16, 136);
                    wmma::mma_sync(acc[nt], a, b, acc[nt]);
                }
            }
#pragma unroll
            for (int nt = 0; nt < 4; nt++) {
                wmma::store_matrix_sync(wb, acc[nt], 16, wmma::mem_row_major);
                __syncwarp();
                const int node = n0 + w * 16 + rr;
                if (node < NN) {
                    const int cc = nh * 64 + nt * 16 + cb;   // col within chunk
                    __half* op = g_mid + (size_t)node * 256 + nc * 128 + cc;
                    const float* wr = wb + rr * 16 + cb;
#pragma unroll
                    for (int c = 0; c < 8; c += 2) {
                        float v0 = fmaxf(wr[c] + sb[cc + c], 0.0f);
                        float v1 = fmaxf(wr[c + 1] + sb[cc + c + 1], 0.0f);
                        *reinterpret_cast<__half2*>(op + c) = __floats2half2_rn(v0, v1);
                    }
                }
                __syncwarp();
            }
        }
    }
}

// ---------------------------------------------------------------------------
// K3: node MLP layer 2: out = relu(g_mid @ W4 + b4), K=256 in 2 chunks
// smem: sIn 128x136 @0 (34816B), sW 128x136 @34816 (34816B),
//       wbuf @69632 (8192B) -> 77824B => 2 CTAs/SM
// ---------------------------------------------------------------------------
#define N2_SIN  0
#define N2_SW   34816
#define N2_WBUF 69632
#define NODE2_SMEM 77824

__global__ __launch_bounds__(256, 2)
void node2_kernel(const float* __restrict__ W4, const float* __restrict__ b4,
                  float* __restrict__ out)
{
    extern __shared__ __align__(128) char smem[];
    __half* sIn = (__half*)(smem + N2_SIN);  // ld 136
    __half* sW  = (__half*)(smem + N2_SW);   // ld 136
    float*  wbuf = (float*)(smem + N2_WBUF);

    __shared__ float sb[128];

    const int t = threadIdx.x;
    const int w = t >> 5, lane = t & 31;
    const int n0 = blockIdx.x * 128;
    float* wb = wbuf + w * 256;

    const int rr = lane >> 1, cb = (lane & 1) * 8;

#pragma unroll 1
    for (int nc = 0; nc < 2; nc++) {
        wmma::fragment<wmma::accumulator, 16, 16, 16, float> acc[8];
#pragma unroll
        for (int nt = 0; nt < 8; nt++) wmma::fill_fragment(acc[nt], 0.0f);

#pragma unroll 1
        for (int kc = 0; kc < 2; kc++) {
            __syncthreads();   // protect previous tiles / epilogue
            for (int i = t; i < 128 * 128; i += 256) {
                int r = i >> 7, c = i & 127;
                int nd = min(n0 + r, NN - 1);
                sIn[r * 136 + c] = g_mid[(size_t)nd * 256 + kc * 128 + c];
            }
            for (int i = t; i < 128 * 128; i += 256) {
                int k = i >> 7, j = i & 127;
                sW[k * 136 + j] = __float2half_rn(W4[(kc * 128 + k) * 256 + nc * 128 + j]);
            }
            if (kc == 0 && t < 128) sb[t] = b4[nc * 128 + t];
            __syncthreads();

#pragma unroll
            for (int kt = 0; kt < 8; kt++) {
                wmma::fragment<wmma::matrix_a, 16, 16, 16, __half, wmma::row_major> a;
                wmma::load_matrix_sync(a, sIn + w * 16 * 136 + kt * 16, 136);
#pragma unroll
                for (int nt = 0; nt < 8; nt++) {
                    wmma::fragment<wmma::matrix_b, 16, 16, 16, __half, wmma::row_major> b;
                    wmma::load_matrix_sync(b, sW + kt * 16 * 136 + nt * 16, 136);
                    wmma::mma_sync(acc[nt], a, b, acc[nt]);
                }
            }
        }

#pragma unroll
        for (int nt = 0; nt < 8; nt++) {
            wmma::store_matrix_sync(wb, acc[nt], 16, wmma::mem_row_major);
            __syncwarp();
            const int node = n0 + w * 16 + rr;
            if (node < NN) {
                const int cc = nt * 16 + cb;
                float* op = out + (size_t)node * 256 + nc * 128 + cc;
                const float* wr = wb + rr * 16 + cb;
                float4 v0 = make_float4(fmaxf(wr[0] + sb[cc + 0], 0.0f),
                                        fmaxf(wr[1] + sb[cc + 1], 0.0f),
                                        fmaxf(wr[2] + sb[cc + 2], 0.0f),
                                        fmaxf(wr[3] + sb[cc + 3], 0.0f));
                float4 v1 = make_float4(fmaxf(wr[4] + sb[cc + 4], 0.0f),
                                        fmaxf(wr[5] + sb[cc + 5], 0.0f),
                                        fmaxf(wr[6] + sb[cc + 6], 0.0f),
                                        fmaxf(wr[7] + sb[cc + 7], 0.0f));
                *reinterpret_cast<float4*>(op) = v0;
                *reinterpret_cast<float4*>(op + 4) = v1;
            }
            __syncwarp();
        }
    }
}

// ---------------------------------------------------------------------------
// launch
// ---------------------------------------------------------------------------
extern "C" void kernel_launch(void* const* d_in, const int* in_sizes, int n_in,
                              void* d_out, int out_size)
{
    const float* x  = (const float*)d_in[0];
    const void*  ei = d_in[1];
    const float* ea = (const float*)d_in[2];
    const float* W1 = (const float*)d_in[3];
    const float* b1 = (const float*)d_in[4];
    const float* W2 = (const float*)d_in[5];
    const float* b2 = (const float*)d_in[6];
    const float* W3 = (const float*)d_in[7];
    const float* b3 = (const float*)d_in[8];
    const float* W4 = (const float*)d_in[9];
    const float* b4 = (const float*)d_in[10];
    float* out = (float*)d_out;

    cudaFuncSetAttribute(edge_kernel,
                         cudaFuncAttributeMaxDynamicSharedMemorySize, EDGE_SMEM);
    cudaFuncSetAttribute(node1_kernel,
                         cudaFuncAttributeMaxDynamicSharedMemorySize, NODE1_SMEM);
    cudaFuncSetAttribute(node2_kernel,
                         cudaFuncAttributeMaxDynamicSharedMemorySize, NODE2_SMEM);

    detect_kernel<<<1, 32>>>((const long long*)ei);
    zero_kernel<<<2048, 256>>>();
    edge_kernel<<<NE / 128, 256, EDGE_SMEM>>>(x, ei, ea, W1, b1, W2, b2);
    node1_kernel<<<(NN + 127) / 128, 256, NODE1_SMEM>>>(x, W3, b3);
    node2_kernel<<<(NN + 127) / 128, 256, NODE2_SMEM>>>(W4, b4, out);
}

// round 16
// speedup vs baseline: 2.8829x; 1.1084x over previous
#include <cuda_runtime.h>
#include <cuda_fp16.h>
#include <mma.h>
#include <cstddef>

using namespace nvcuda;

#define NN 100000
#define NE 1600000

// Scratch (allocation-free rule: __device__ globals)
__device__ float  g_acc[(size_t)NN * 128];   // segment sums  [N,128]
__device__ float  g_cnt[NN];                 // segment counts
__device__ __half g_mid[(size_t)NN * 256];   // node MLP hidden [N,256] fp16
__device__ int    g_is64;                    // edge_index dtype flag

// Pre-converted fp16 weights, padded to the exact smem tile layouts
__device__ __align__(16) __half pW1[48 * 72];            // [48][72]
__device__ __align__(16) __half pW2[64 * 136];           // [64][136]
__device__ __align__(16) __half pW3[2 * 144 * 136];      // [nc][144][136]
__device__ __align__(16) __half pW4[4 * 128 * 136];      // [kc*2+nc][128][136]

// ---------------------------------------------------------------------------
// K-1: detect edge_index dtype (int64 vs int32)
// ---------------------------------------------------------------------------
__global__ void detect_kernel(const long long* __restrict__ ei)
{
    if (threadIdx.x == 0 && blockIdx.x == 0) {
        int ok = 1;
        for (int i = 0; i < 128; i++) {
            long long v = ei[i];
            if (v < 0 || v >= NN) { ok = 0; break; }
        }
        g_is64 = ok;
    }
}

// ---------------------------------------------------------------------------
// K-0.5: pre-convert weights to padded fp16 tiles (runs every call; cheap)
// ---------------------------------------------------------------------------
__global__ void prep_kernel(const float* __restrict__ W1,
                            const float* __restrict__ W2,
                            const float* __restrict__ W3,
                            const float* __restrict__ W4)
{
    const int t = blockIdx.x * blockDim.x + threadIdx.x;
    const int stride = gridDim.x * blockDim.x;

    for (int i = t; i < 48 * 72; i += stride) {
        int k = i / 72, j = i - k * 72;
        pW1[i] = (k < 43 && j < 64) ? __float2half_rn(W1[k * 64 + j]) : __half(0.0f);
    }
    for (int i = t; i < 64 * 136; i += stride) {
        int k = i / 136, j = i - k * 136;
        pW2[i] = (j < 128) ? __float2half_rn(W2[k * 128 + j]) : __half(0.0f);
    }
    for (int i = t; i < 2 * 144 * 136; i += stride) {
        int nc = i / (144 * 136), rem = i - nc * 144 * 136;
        int k = rem / 136, j = rem - k * 136;
        pW3[i] = (k < 132 && j < 128)
                 ? __float2half_rn(W3[k * 256 + nc * 128 + j]) : __half(0.0f);
    }
    for (int i = t; i < 4 * 128 * 136; i += stride) {
        int q = i / (128 * 136), rem = i - q * 128 * 136;
        int kc = q >> 1, nc = q & 1;
        int k = rem / 136, j = rem - k * 136;
        pW4[i] = (j < 128)
                 ? __float2half_rn(W4[(kc * 128 + k) * 256 + nc * 128 + j])
                 : __half(0.0f);
    }
}

// ---------------------------------------------------------------------------
// K0: zero accumulators
// ---------------------------------------------------------------------------
__global__ void zero_kernel()
{
    size_t i = (size_t)blockIdx.x * blockDim.x + threadIdx.x;
    size_t stride = (size_t)gridDim.x * blockDim.x;
    for (size_t k = i; k < (size_t)NN * 128; k += stride) g_acc[k] = 0.0f;
    for (size_t k = i; k < (size_t)NN; k += stride) g_cnt[k] = 0.0f;
}

// ---------------------------------------------------------------------------
// K1: edge MLP (wmma, M=256 edges/block) + scatter
// smem: sA 256x56 @0 (28672B), sW1 48x72 @28672 (6912B),
//       sH 256x72 @35584 (36864B), sW2 64x136 @72448 (17408B),
//       wbuf @89856 (8192B) -> 98048B => 2 CTAs/SM
// ---------------------------------------------------------------------------
#define E_SA   0
#define E_SW1  28672
#define E_SH   35584
#define E_SW2  72448
#define E_WBUF 89856
#define EDGE_SMEM 98048

__global__ __launch_bounds__(256, 2)
void edge_kernel(const float* __restrict__ x,
                 const void* __restrict__ ei_raw,
                 const float* __restrict__ ea,
                 const float* __restrict__ b1, const float* __restrict__ b2)
{
    extern __shared__ __align__(128) char smem[];
    __half* sA  = (__half*)(smem + E_SA);    // ld 56
    __half* sW1 = (__half*)(smem + E_SW1);   // ld 72
    __half* sH  = (__half*)(smem + E_SH);    // ld 72
    __half* sW2 = (__half*)(smem + E_SW2);   // ld 136
    float*  wbuf = (float*)(smem + E_WBUF);

    __shared__ int   sDst[256], sSrc[256];
    __shared__ float sb1s[64], sb2s[128];

    const int t = threadIdx.x;
    const int w = t >> 5, lane = t & 31;
    const int e0 = blockIdx.x * 256;          // NE = 6250*256 exactly
    float* wb = wbuf + w * 256;

    {
        int e = e0 + t, d, s;
        if (g_is64) {
            const long long* ei = (const long long*)ei_raw;
            d = (int)ei[e]; s = (int)ei[NE + e];
        } else {
            const int* ei = (const int*)ei_raw;
            d = ei[e]; s = ei[NE + e];
        }
        sDst[t] = min(max(d, 0), NN - 1);
        sSrc[t] = min(max(s, 0), NN - 1);
    }
    if (t < 64) sb1s[t] = b1[t];
    if (t >= 128) sb2s[t - 128] = b2[t - 128];

    // weight copies (pure uint4 moves, pre-padded fp16)
    {
        const uint4* g1 = (const uint4*)pW1; uint4* s1 = (uint4*)sW1;
        for (int i = t; i < 48 * 72 / 8; i += 256) s1[i] = g1[i];
        const uint4* g2 = (const uint4*)pW2; uint4* s2 = (uint4*)sW2;
        for (int i = t; i < 64 * 136 / 8; i += 256) s2[i] = g2[i];
    }
    __syncthreads();   // sSrc ready

    // A fill: 256 rows x 48 cols
    for (int i = t; i < 256 * 48; i += 256) {
        int r = i / 48, c = i - r * 48;
        float v;
        if (c < 4)       v = x[(size_t)sSrc[r] * 4 + c];
        else if (c < 43) v = ea[(size_t)(e0 + r) * 39 + (c - 4)];
        else             v = 0.0f;
        sA[r * 56 + c] = __float2half_rn(v);
    }
    __syncthreads();

    const int rr = lane >> 1, cb = (lane & 1) * 8;

    // --- GEMM1: warp w owns rows [32w, 32w+32) as 2 M-tiles ---
    {
        wmma::fragment<wmma::accumulator, 16, 16, 16, float> c1[2][4];
#pragma unroll
        for (int mm = 0; mm < 2; mm++)
#pragma unroll
            for (int nt = 0; nt < 4; nt++) wmma::fill_fragment(c1[mm][nt], 0.0f);
#pragma unroll
        for (int kt = 0; kt < 3; kt++) {
            wmma::fragment<wmma::matrix_a, 16, 16, 16, __half, wmma::row_major> a[2];
#pragma unroll
            for (int mm = 0; mm < 2; mm++)
                wmma::load_matrix_sync(a[mm], sA + (w * 32 + mm * 16) * 56 + kt * 16, 56);
#pragma unroll
            for (int nt = 0; nt < 4; nt++) {
                wmma::fragment<wmma::matrix_b, 16, 16, 16, __half, wmma::row_major> b;
                wmma::load_matrix_sync(b, sW1 + kt * 16 * 72 + nt * 16, 72);
#pragma unroll
                for (int mm = 0; mm < 2; mm++)
                    wmma::mma_sync(c1[mm][nt], a[mm], b, c1[mm][nt]);
            }
        }
#pragma unroll
        for (int mm = 0; mm < 2; mm++)
#pragma unroll
            for (int nt = 0; nt < 4; nt++) {
                wmma::store_matrix_sync(wb, c1[mm][nt], 16, wmma::mem_row_major);
                __syncwarp();
#pragma unroll
                for (int c = 0; c < 8; c++) {
                    float v = wb[rr * 16 + cb + c] + sb1s[nt * 16 + cb + c];
                    sH[(w * 32 + mm * 16 + rr) * 72 + nt * 16 + cb + c] =
                        __float2half_rn(fmaxf(v, 0.0f));
                }
                __syncwarp();
            }
    }
    __syncthreads();

    // --- GEMM2: K=64, N=128 in 2 halves, bias+relu+atomic scatter ---
#pragma unroll 1
    for (int nh = 0; nh < 2; nh++) {
        wmma::fragment<wmma::accumulator, 16, 16, 16, float> c2[2][4];
#pragma unroll
        for (int mm = 0; mm < 2; mm++)
#pragma unroll
            for (int nt = 0; nt < 4; nt++) wmma::fill_fragment(c2[mm][nt], 0.0f);
#pragma unroll
        for (int kt = 0; kt < 4; kt++) {
            wmma::fragment<wmma::matrix_a, 16, 16, 16, __half, wmma::row_major> a[2];
#pragma unroll
            for (int mm = 0; mm < 2; mm++)
                wmma::load_matrix_sync(a[mm], sH + (w * 32 + mm * 16) * 72 + kt * 16, 72);
#pragma unroll
            for (int nt = 0; nt < 4; nt++) {
                wmma::fragment<wmma::matrix_b, 16, 16, 16, __half, wmma::row_major> b;
                wmma::load_matrix_sync(b, sW2 + kt * 16 * 136 + nh * 64 + nt * 16, 136);
#pragma unroll
                for (int mm = 0; mm < 2; mm++)
                    wmma::mma_sync(c2[mm][nt], a[mm], b, c2[mm][nt]);
            }
        }
#pragma unroll
        for (int mm = 0; mm < 2; mm++)
#pragma unroll
            for (int nt = 0; nt < 4; nt++) {
                wmma::store_matrix_sync(wb, c2[mm][nt], 16, wmma::mem_row_major);
                __syncwarp();
                const int colb = nh * 64 + nt * 16 + cb;
                const int dst = sDst[w * 32 + mm * 16 + rr];
                float* ab = g_acc + (size_t)dst * 128 + colb;
                const float* wr = wb + rr * 16 + cb;
                const float* bb = sb2s + colb;
                float4 v0 = make_float4(fmaxf(wr[0] + bb[0], 0.0f),
                                        fmaxf(wr[1] + bb[1], 0.0f),
                                        fmaxf(wr[2] + bb[2], 0.0f),
                                        fmaxf(wr[3] + bb[3], 0.0f));
                float4 v1 = make_float4(fmaxf(wr[4] + bb[4], 0.0f),
                                        fmaxf(wr[5] + bb[5], 0.0f),
                                        fmaxf(wr[6] + bb[6], 0.0f),
                                        fmaxf(wr[7] + bb[7], 0.0f));
                atomicAdd(reinterpret_cast<float4*>(ab), v0);
                atomicAdd(reinterpret_cast<float4*>(ab + 4), v1);
                __syncwarp();
            }
    }
    atomicAdd(&g_cnt[sDst[t]], 1.0f);
}

// ---------------------------------------------------------------------------
// K2: node MLP layer 1: in=[x|mean|0] (144), out=relu(in@W3+b3) -> g_mid fp16
// smem: sIn 128x152 @0 (38912B), sW 144x136 @38912 (39168B),
//       wbuf @78080 (8192B) -> 86272B => 2 CTAs/SM
// ---------------------------------------------------------------------------
#define N1_SIN  0
#define N1_SW   38912
#define N1_WBUF 78080
#define NODE1_SMEM 86272

__global__ __launch_bounds__(256, 2)
void node1_kernel(const float* __restrict__ x, const float* __restrict__ b3)
{
    extern __shared__ __align__(128) char smem[];
    __half* sIn = (__half*)(smem + N1_SIN);  // ld 152
    __half* sW  = (__half*)(smem + N1_SW);   // ld 136
    float*  wbuf = (float*)(smem + N1_WBUF);

    __shared__ float sInv[128];
    __shared__ float sb[128];

    const int t = threadIdx.x;
    const int w = t >> 5, lane = t & 31;
    const int n0 = blockIdx.x * 128;
    float* wb = wbuf + w * 256;

    if (t < 128) {
        int nd = min(n0 + t, NN - 1);
        sInv[t] = 1.0f / fmaxf(g_cnt[nd], 1.0f);
    }
    __syncthreads();

    // in-row: [x(4) | mean(128) | zeros(12..)] — cols 132..143 explicitly 0
    for (int i = t; i < 128 * 144; i += 256) {
        int r = i / 144, c = i - r * 144;
        int nd = min(n0 + r, NN - 1);
        float v;
        if (c < 4)        v = x[(size_t)nd * 4 + c];
        else if (c < 132) v = g_acc[(size_t)nd * 128 + (c - 4)] * sInv[r];
        else              v = 0.0f;
        sIn[r * 152 + c] = __float2half_rn(v);
    }
    // zero pad cols 144..151 (never written above)
    for (int r = t; r < 128; r += 256) {
        *reinterpret_cast<uint4*>(sIn + r * 152 + 144) = make_uint4(0, 0, 0, 0);
    }

    const int rr = lane >> 1, cb = (lane & 1) * 8;

#pragma unroll 1
    for (int nc = 0; nc < 2; nc++) {
        __syncthreads();   // sIn ready / previous chunk done
        {
            const uint4* gsrc = (const uint4*)(pW3 + nc * 144 * 136);
            uint4* sdst = (uint4*)sW;
            for (int i = t; i < 144 * 136 / 8; i += 256) sdst[i] = gsrc[i];
        }
        if (t < 128) sb[t] = b3[nc * 128 + t];
        __syncthreads();

#pragma unroll 1
        for (int nh = 0; nh < 2; nh++) {
            wmma::fragment<wmma::accumulator, 16, 16, 16, float> acc[4];
#pragma unroll
            for (int nt = 0; nt < 4; nt++) wmma::fill_fragment(acc[nt], 0.0f);
#pragma unroll
            for (int kt = 0; kt < 9; kt++) {
                wmma::fragment<wmma::matrix_a, 16, 16, 16, __half, wmma::row_major> a;
                wmma::load_matrix_sync(a, sIn + w * 16 * 152 + kt * 16, 152);
#pragma unroll
                for (int nt = 0; nt < 4; nt++) {
                    wmma::fragment<wmma::matrix_b, 16, 16, 16, __half, wmma::row_major> b;
                    wmma::load_matrix_sync(b, sW + kt * 16 * 136 + nh * 64 + nt * 16, 136);
                    wmma::mma_sync(acc[nt], a, b, acc[nt]);
                }
            }
#pragma unroll
            for (int nt = 0; nt < 4; nt++) {
                wmma::store_matrix_sync(wb, acc[nt], 16, wmma::mem_row_major);
                __syncwarp();
                const int node = n0 + w * 16 + rr;
                if (node < NN) {
                    const int cc = nh * 64 + nt * 16 + cb;
                    __half* op = g_mid + (size_t)node * 256 + nc * 128 + cc;
                    const float* wr = wb + rr * 16 + cb;
#pragma unroll
                    for (int c = 0; c < 8; c += 2) {
                        float v0 = fmaxf(wr[c] + sb[cc + c], 0.0f);
                        float v1 = fmaxf(wr[c + 1] + sb[cc + c + 1], 0.0f);
                        *reinterpret_cast<__half2*>(op + c) = __floats2half2_rn(v0, v1);
                    }
                }
                __syncwarp();
            }
        }
    }
}

// ---------------------------------------------------------------------------
// K3: node MLP layer 2: out = relu(g_mid @ W4 + b4), K=256 in 2 chunks
// smem: sIn 128x136 @0 (34816B), sW 128x136 @34816 (34816B),
//       wbuf @69632 (8192B) -> 77824B => 2 CTAs/SM
// ---------------------------------------------------------------------------
#define N2_SIN  0
#define N2_SW   34816
#define N2_WBUF 69632
#define NODE2_SMEM 77824

__global__ __launch_bounds__(256, 2)
void node2_kernel(const float* __restrict__ b4, float* __restrict__ out)
{
    extern __shared__ __align__(128) char smem[];
    __half* sIn = (__half*)(smem + N2_SIN);  // ld 136
    __half* sW  = (__half*)(smem + N2_SW);   // ld 136
    float*  wbuf = (float*)(smem + N2_WBUF);

    __shared__ float sb[128];

    const int t = threadIdx.x;
    const int w = t >> 5, lane = t & 31;
    const int n0 = blockIdx.x * 128;
    float* wb = wbuf + w * 256;

    const int rr = lane >> 1, cb = (lane & 1) * 8;

#pragma unroll 1
    for (int nc = 0; nc < 2; nc++) {
        wmma::fragment<wmma::accumulator, 16, 16, 16, float> acc[8];
#pragma unroll
        for (int nt = 0; nt < 8; nt++) wmma::fill_fragment(acc[nt], 0.0f);

#pragma unroll 1
        for (int kc = 0; kc < 2; kc++) {
            __syncthreads();
            // sIn: vectorized row copies from g_mid.
            // A 128-col half row = 256 B = 16 uint4  (R7 bug: was 8 -> half the
            // row uninitialized -> inf). Now 128*16 uint4 total.
            for (int i = t; i < 128 * 16; i += 256) {
                int r = i >> 4, v = i & 15;
                int nd = min(n0 + r, NN - 1);
                reinterpret_cast<uint4*>(sIn + r * 136)[v] =
                    reinterpret_cast<const uint4*>(g_mid + (size_t)nd * 256 + kc * 128)[v];
            }
            {
                const uint4* gsrc = (const uint4*)(pW4 + (kc * 2 + nc) * 128 * 136);
                uint4* sdst = (uint4*)sW;
                for (int i = t; i < 128 * 136 / 8; i += 256) sdst[i] = gsrc[i];
            }
            if (kc == 0 && t < 128) sb[t] = b4[nc * 128 + t];
            __syncthreads();

#pragma unroll
            for (int kt = 0; kt < 8; kt++) {
                wmma::fragment<wmma::matrix_a, 16, 16, 16, __half, wmma::row_major> a;
                wmma::load_matrix_sync(a, sIn + w * 16 * 136 + kt * 16, 136);
#pragma unroll
                for (int nt = 0; nt < 8; nt++) {
                    wmma::fragment<wmma::matrix_b, 16, 16, 16, __half, wmma::row_major> b;
                    wmma::load_matrix_sync(b, sW + kt * 16 * 136 + nt * 16, 136);
                    wmma::mma_sync(acc[nt], a, b, acc[nt]);
                }
            }
        }

#pragma unroll
        for (int nt = 0; nt < 8; nt++) {
            wmma::store_matrix_sync(wb, acc[nt], 16, wmma::mem_row_major);
            __syncwarp();
            const int node = n0 + w * 16 + rr;
            if (node < NN) {
                const int cc = nt * 16 + cb;
                float* op = out + (size_t)node * 256 + nc * 128 + cc;
                const float* wr = wb + rr * 16 + cb;
                float4 v0 = make_float4(fmaxf(wr[0] + sb[cc + 0], 0.0f),
                                        fmaxf(wr[1] + sb[cc + 1], 0.0f),
                                        fmaxf(wr[2] + sb[cc + 2], 0.0f),
                                        fmaxf(wr[3] + sb[cc + 3], 0.0f));
                float4 v1 = make_float4(fmaxf(wr[4] + sb[cc + 4], 0.0f),
                                        fmaxf(wr[5] + sb[cc + 5], 0.0f),
                                        fmaxf(wr[6] + sb[cc + 6], 0.0f),
                                        fmaxf(wr[7] + sb[cc + 7], 0.0f));
                *reinterpret_cast<float4*>(op) = v0;
                *reinterpret_cast<float4*>(op + 4) = v1;
            }
            __syncwarp();
        }
    }
}

// ---------------------------------------------------------------------------
// launch
// ---------------------------------------------------------------------------
extern "C" void kernel_launch(void* const* d_in, const int* in_sizes, int n_in,
                              void* d_out, int out_size)
{
    const float* x  = (const float*)d_in[0];
    const void*  ei = d_in[1];
    const float* ea = (const float*)d_in[2];
    const float* W1 = (const float*)d_in[3];
    const float* b1 = (const float*)d_in[4];
    const float* W2 = (const float*)d_in[5];
    const float* b2 = (const float*)d_in[6];
    const float* W3 = (const float*)d_in[7];
    const float* b3 = (const float*)d_in[8];
    const float* W4 = (const float*)d_in[9];
    const float* b4 = (const float*)d_in[10];
    float* out = (float*)d_out;

    cudaFuncSetAttribute(edge_kernel,
                         cudaFuncAttributeMaxDynamicSharedMemorySize, EDGE_SMEM);
    cudaFuncSetAttribute(node1_kernel,
                         cudaFuncAttributeMaxDynamicSharedMemorySize, NODE1_SMEM);
    cudaFuncSetAttribute(node2_kernel,
                         cudaFuncAttributeMaxDynamicSharedMemorySize, NODE2_SMEM);

    detect_kernel<<<1, 32>>>((const long long*)ei);
    prep_kernel<<<64, 256>>>(W1, W2, W3, W4);
    zero_kernel<<<2048, 256>>>();
    edge_kernel<<<NE / 256, 256, EDGE_SMEM>>>(x, ei, ea, b1, b2);
    node1_kernel<<<(NN + 127) / 128, 256, NODE1_SMEM>>>(x, b3);
    node2_kernel<<<(NN + 127) / 128, 256, NODE2_SMEM>>>(b4, out);
}

// round 17
// speedup vs baseline: 3.3077x; 1.1474x over previous
#include <cuda_runtime.h>
#include <cuda_fp16.h>
#include <mma.h>
#include <cstddef>

using namespace nvcuda;

#define NN 100000
#define NE 1600000

__device__ float  g_acc[(size_t)NN * 128];   // segment sums  [N,128]
__device__ float  g_cnt[NN];                 // segment counts
__device__ __half g_mid[(size_t)NN * 256];   // node MLP hidden [N,256] fp16
__device__ int    g_is64;                    // edge_index dtype flag

// Pre-converted fp16 weights, padded to the exact smem tile layouts
__device__ __align__(16) __half pW1[48 * 72];
__device__ __align__(16) __half pW2[64 * 136];
__device__ __align__(16) __half pW3[2 * 144 * 136];
__device__ __align__(16) __half pW4[4 * 128 * 136];

__device__ __forceinline__ float4 relu4_add(float4 v, float4 b)
{
    return make_float4(fmaxf(v.x + b.x, 0.0f), fmaxf(v.y + b.y, 0.0f),
                       fmaxf(v.z + b.z, 0.0f), fmaxf(v.w + b.w, 0.0f));
}

// ---------------------------------------------------------------------------
__global__ void detect_kernel(const long long* __restrict__ ei)
{
    if (threadIdx.x == 0 && blockIdx.x == 0) {
        int ok = 1;
        for (int i = 0; i < 128; i++) {
            long long v = ei[i];
            if (v < 0 || v >= NN) { ok = 0; break; }
        }
        g_is64 = ok;
    }
}

// ---------------------------------------------------------------------------
__global__ void prep_kernel(const float* __restrict__ W1,
                            const float* __restrict__ W2,
                            const float* __restrict__ W3,
                            const float* __restrict__ W4)
{
    const int t = blockIdx.x * blockDim.x + threadIdx.x;
    const int stride = gridDim.x * blockDim.x;

    for (int i = t; i < 48 * 72; i += stride) {
        int k = i / 72, j = i - k * 72;
        pW1[i] = (k < 43 && j < 64) ? __float2half_rn(W1[k * 64 + j]) : __half(0.0f);
    }
    for (int i = t; i < 64 * 136; i += stride) {
        int k = i / 136, j = i - k * 136;
        pW2[i] = (j < 128) ? __float2half_rn(W2[k * 128 + j]) : __half(0.0f);
    }
    for (int i = t; i < 2 * 144 * 136; i += stride) {
        int nc = i / (144 * 136), rem = i - nc * 144 * 136;
        int k = rem / 136, j = rem - k * 136;
        pW3[i] = (k < 132 && j < 128)
                 ? __float2half_rn(W3[k * 256 + nc * 128 + j]) : __half(0.0f);
    }
    for (int i = t; i < 4 * 128 * 136; i += stride) {
        int q = i / (128 * 136), rem = i - q * 128 * 136;
        int kc = q >> 1, nc = q & 1;
        int k = rem / 136, j = rem - k * 136;
        pW4[i] = (j < 128)
                 ? __float2half_rn(W4[(kc * 128 + k) * 256 + nc * 128 + j])
                 : __half(0.0f);
    }
}

// ---------------------------------------------------------------------------
__global__ void zero_kernel()
{
    size_t i = (size_t)blockIdx.x * blockDim.x + threadIdx.x;
    size_t stride = (size_t)gridDim.x * blockDim.x;
    for (size_t k = i; k < (size_t)NN * 128; k += stride) g_acc[k] = 0.0f;
    for (size_t k = i; k < (size_t)NN; k += stride) g_cnt[k] = 0.0f;
}

// ---------------------------------------------------------------------------
// K1: edge MLP (wmma, M=256 edges/block) + scatter
// smem layout unchanged from R16 (98048B, 2 CTAs/SM). Epilogues rewritten:
// lane mapping row=lane>>2 (+8), chunk=(lane&3)*4 -> conflict-free LDS.128.
// ---------------------------------------------------------------------------
#define E_SA   0
#define E_SW1  28672
#define E_SH   35584
#define E_SW2  72448
#define E_WBUF 89856
#define EDGE_SMEM 98048

__global__ __launch_bounds__(256, 2)
void edge_kernel(const float* __restrict__ x,
                 const void* __restrict__ ei_raw,
                 const float* __restrict__ ea,
                 const float* __restrict__ b1, const float* __restrict__ b2)
{
    extern __shared__ __align__(128) char smem[];
    __half* sA  = (__half*)(smem + E_SA);    // ld 56
    __half* sW1 = (__half*)(smem + E_SW1);   // ld 72
    __half* sH  = (__half*)(smem + E_SH);    // ld 72
    __half* sW2 = (__half*)(smem + E_SW2);   // ld 136
    float*  wbuf = (float*)(smem + E_WBUF);

    __shared__ int   sDst[256], sSrc[256];
    __shared__ float sb1s[64], sb2s[128];

    const int t = threadIdx.x;
    const int w = t >> 5, lane = t & 31;
    const int e0 = blockIdx.x * 256;          // NE = 6250*256 exactly
    float* wb = wbuf + w * 256;

    {
        int e = e0 + t, d, s;
        if (g_is64) {
            const long long* ei = (const long long*)ei_raw;
            d = (int)ei[e]; s = (int)ei[NE + e];
        } else {
            const int* ei = (const int*)ei_raw;
            d = ei[e]; s = ei[NE + e];
        }
        sDst[t] = min(max(d, 0), NN - 1);
        sSrc[t] = min(max(s, 0), NN - 1);
    }
    if (t < 64) sb1s[t] = b1[t];
    if (t >= 128) sb2s[t - 128] = b2[t - 128];

    {
        const uint4* g1 = (const uint4*)pW1; uint4* s1 = (uint4*)sW1;
        for (int i = t; i < 48 * 72 / 8; i += 256) s1[i] = g1[i];
        const uint4* g2 = (const uint4*)pW2; uint4* s2 = (uint4*)sW2;
        for (int i = t; i < 64 * 136 / 8; i += 256) s2[i] = g2[i];
    }
    __syncthreads();   // sSrc ready

    for (int i = t; i < 256 * 48; i += 256) {
        int r = i / 48, c = i - r * 48;
        float v;
        if (c < 4)       v = x[(size_t)sSrc[r] * 4 + c];
        else if (c < 43) v = ea[(size_t)(e0 + r) * 39 + (c - 4)];
        else             v = 0.0f;
        sA[r * 56 + c] = __float2half_rn(v);
    }
    __syncthreads();

    const int erow = lane >> 2;          // 0..7 (+8 on second pass)
    const int c4   = (lane & 3) * 4;     // 4-float chunk within 16 cols

    // --- GEMM1: warp w owns rows [32w, 32w+32) as 2 M-tiles ---
    {
        wmma::fragment<wmma::accumulator, 16, 16, 16, float> c1[2][4];
#pragma unroll
        for (int mm = 0; mm < 2; mm++)
#pragma unroll
            for (int nt = 0; nt < 4; nt++) wmma::fill_fragment(c1[mm][nt], 0.0f);
#pragma unroll
        for (int kt = 0; kt < 3; kt++) {
            wmma::fragment<wmma::matrix_a, 16, 16, 16, __half, wmma::row_major> a[2];
#pragma unroll
            for (int mm = 0; mm < 2; mm++)
                wmma::load_matrix_sync(a[mm], sA + (w * 32 + mm * 16) * 56 + kt * 16, 56);
#pragma unroll
            for (int nt = 0; nt < 4; nt++) {
                wmma::fragment<wmma::matrix_b, 16, 16, 16, __half, wmma::row_major> b;
                wmma::load_matrix_sync(b, sW1 + kt * 16 * 72 + nt * 16, 72);
#pragma unroll
                for (int mm = 0; mm < 2; mm++)
                    wmma::mma_sync(c1[mm][nt], a[mm], b, c1[mm][nt]);
            }
        }
#pragma unroll
        for (int mm = 0; mm < 2; mm++)
#pragma unroll
            for (int nt = 0; nt < 4; nt++) {
                wmma::store_matrix_sync(wb, c1[mm][nt], 16, wmma::mem_row_major);
                __syncwarp();
                const float4 bias = *reinterpret_cast<const float4*>(sb1s + nt * 16 + c4);
#pragma unroll
                for (int h = 0; h < 16; h += 8) {
                    float4 v = *reinterpret_cast<const float4*>(wb + (erow + h) * 16 + c4);
                    v = relu4_add(v, bias);
                    __half2 p0 = __floats2half2_rn(v.x, v.y);
                    __half2 p1 = __floats2half2_rn(v.z, v.w);
                    __half* hp = sH + (w * 32 + mm * 16 + erow + h) * 72 + nt * 16 + c4;
                    *reinterpret_cast<__half2*>(hp)     = p0;
                    *reinterpret_cast<__half2*>(hp + 2) = p1;
                }
                __syncwarp();
            }
    }
    __syncthreads();

    // --- GEMM2: K=64, N=128 in 2 halves, bias+relu+atomic scatter ---
#pragma unroll 1
    for (int nh = 0; nh < 2; nh++) {
        wmma::fragment<wmma::accumulator, 16, 16, 16, float> c2[2][4];
#pragma unroll
        for (int mm = 0; mm < 2; mm++)
#pragma unroll
            for (int nt = 0; nt < 4; nt++) wmma::fill_fragment(c2[mm][nt], 0.0f);
#pragma unroll
        for (int kt = 0; kt < 4; kt++) {
            wmma::fragment<wmma::matrix_a, 16, 16, 16, __half, wmma::row_major> a[2];
#pragma unroll
            for (int mm = 0; mm < 2; mm++)
                wmma::load_matrix_sync(a[mm], sH + (w * 32 + mm * 16) * 72 + kt * 16, 72);
#pragma unroll
            for (int nt = 0; nt < 4; nt++) {
                wmma::fragment<wmma::matrix_b, 16, 16, 16, __half, wmma::row_major> b;
                wmma::load_matrix_sync(b, sW2 + kt * 16 * 136 + nh * 64 + nt * 16, 136);
#pragma unroll
                for (int mm = 0; mm < 2; mm++)
                    wmma::mma_sync(c2[mm][nt], a[mm], b, c2[mm][nt]);
            }
        }
#pragma unroll
        for (int mm = 0; mm < 2; mm++)
#pragma unroll
            for (int nt = 0; nt < 4; nt++) {
                wmma::store_matrix_sync(wb, c2[mm][nt], 16, wmma::mem_row_major);
                __syncwarp();
                const int colb = nh * 64 + nt * 16 + c4;
                const float4 bias = *reinterpret_cast<const float4*>(sb2s + colb);
#pragma unroll
                for (int h = 0; h < 16; h += 8) {
                    float4 v = *reinterpret_cast<const float4*>(wb + (erow + h) * 16 + c4);
                    v = relu4_add(v, bias);
                    const int dst = sDst[w * 32 + mm * 16 + erow + h];
                    atomicAdd(reinterpret_cast<float4*>(
                                  g_acc + (size_t)dst * 128 + colb), v);
                }
                __syncwarp();
            }
    }
    atomicAdd(&g_cnt[sDst[t]], 1.0f);
}

// ---------------------------------------------------------------------------
// K2: node MLP layer 1: in=[x|mean|0] (144), out=relu(in@W3+b3) -> g_mid fp16
// ---------------------------------------------------------------------------
#define N1_SIN  0
#define N1_SW   38912
#define N1_WBUF 78080
#define NODE1_SMEM 86272

__global__ __launch_bounds__(256, 2)
void node1_kernel(const float* __restrict__ x, const float* __restrict__ b3)
{
    extern __shared__ __align__(128) char smem[];
    __half* sIn = (__half*)(smem + N1_SIN);  // ld 152
    __half* sW  = (__half*)(smem + N1_SW);   // ld 136
    float*  wbuf = (float*)(smem + N1_WBUF);

    __shared__ float sInv[128];
    __shared__ float sb[128];

    const int t = threadIdx.x;
    const int w = t >> 5, lane = t & 31;
    const int n0 = blockIdx.x * 128;
    float* wb = wbuf + w * 256;

    if (t < 128) {
        int nd = min(n0 + t, NN - 1);
        sInv[t] = 1.0f / fmaxf(g_cnt[nd], 1.0f);
    }
    __syncthreads();

    for (int i = t; i < 128 * 144; i += 256) {
        int r = i / 144, c = i - r * 144;
        int nd = min(n0 + r, NN - 1);
        float v;
        if (c < 4)        v = x[(size_t)nd * 4 + c];
        else if (c < 132) v = g_acc[(size_t)nd * 128 + (c - 4)] * sInv[r];
        else              v = 0.0f;
        sIn[r * 152 + c] = __float2half_rn(v);
    }
    for (int r = t; r < 128; r += 256) {
        *reinterpret_cast<uint4*>(sIn + r * 152 + 144) = make_uint4(0, 0, 0, 0);
    }

    const int erow = lane >> 2;
    const int c4   = (lane & 3) * 4;

#pragma unroll 1
    for (int nc = 0; nc < 2; nc++) {
        __syncthreads();
        {
            const uint4* gsrc = (const uint4*)(pW3 + nc * 144 * 136);
            uint4* sdst = (uint4*)sW;
            for (int i = t; i < 144 * 136 / 8; i += 256) sdst[i] = gsrc[i];
        }
        if (t < 128) sb[t] = b3[nc * 128 + t];
        __syncthreads();

#pragma unroll 1
        for (int nh = 0; nh < 2; nh++) {
            wmma::fragment<wmma::accumulator, 16, 16, 16, float> acc[4];
#pragma unroll
            for (int nt = 0; nt < 4; nt++) wmma::fill_fragment(acc[nt], 0.0f);
#pragma unroll
            for (int kt = 0; kt < 9; kt++) {
                wmma::fragment<wmma::matrix_a, 16, 16, 16, __half, wmma::row_major> a;
                wmma::load_matrix_sync(a, sIn + w * 16 * 152 + kt * 16, 152);
#pragma unroll
                for (int nt = 0; nt < 4; nt++) {
                    wmma::fragment<wmma::matrix_b, 16, 16, 16, __half, wmma::row_major> b;
                    wmma::load_matrix_sync(b, sW + kt * 16 * 136 + nh * 64 + nt * 16, 136);
                    wmma::mma_sync(acc[nt], a, b, acc[nt]);
                }
            }
#pragma unroll
            for (int nt = 0; nt < 4; nt++) {
                wmma::store_matrix_sync(wb, acc[nt], 16, wmma::mem_row_major);
                __syncwarp();
                const int cc = nh * 64 + nt * 16 + c4;
                const float4 bias = *reinterpret_cast<const float4*>(sb + cc);
#pragma unroll
                for (int h = 0; h < 16; h += 8) {
                    const int node = n0 + w * 16 + erow + h;
                    if (node < NN) {
                        float4 v = *reinterpret_cast<const float4*>(wb + (erow + h) * 16 + c4);
                        v = relu4_add(v, bias);
                        __half2 p0 = __floats2half2_rn(v.x, v.y);
                        __half2 p1 = __floats2half2_rn(v.z, v.w);
                        __half* op = g_mid + (size_t)node * 256 + nc * 128 + cc;
                        *reinterpret_cast<__half2*>(op)     = p0;
                        *reinterpret_cast<__half2*>(op + 2) = p1;
                    }
                }
                __syncwarp();
            }
        }
    }
}

// ---------------------------------------------------------------------------
// K3: node MLP layer 2: out = relu(g_mid @ W4 + b4), K=256 in 2 chunks
// ---------------------------------------------------------------------------
#define N2_SIN  0
#define N2_SW   34816
#define N2_WBUF 69632
#define NODE2_SMEM 77824

__global__ __launch_bounds__(256, 2)
void node2_kernel(const float* __restrict__ b4, float* __restrict__ out)
{
    extern __shared__ __align__(128) char smem[];
    __half* sIn = (__half*)(smem + N2_SIN);  // ld 136
    __half* sW  = (__half*)(smem + N2_SW);   // ld 136
    float*  wbuf = (float*)(smem + N2_WBUF);

    __shared__ float sb[128];

    const int t = threadIdx.x;
    const int w = t >> 5, lane = t & 31;
    const int n0 = blockIdx.x * 128;
    float* wb = wbuf + w * 256;

    const int erow = lane >> 2;
    const int c4   = (lane & 3) * 4;

#pragma unroll 1
    for (int nc = 0; nc < 2; nc++) {
        wmma::fragment<wmma::accumulator, 16, 16, 16, float> acc[8];
#pragma unroll
        for (int nt = 0; nt < 8; nt++) wmma::fill_fragment(acc[nt], 0.0f);

#pragma unroll 1
        for (int kc = 0; kc < 2; kc++) {
            __syncthreads();
            // 128-col half row = 256 B = 16 uint4 per row
            for (int i = t; i < 128 * 16; i += 256) {
                int r = i >> 4, v = i & 15;
                int nd = min(n0 + r, NN - 1);
                reinterpret_cast<uint4*>(sIn + r * 136)[v] =
                    reinterpret_cast<const uint4*>(g_mid + (size_t)nd * 256 + kc * 128)[v];
            }
            {
                const uint4* gsrc = (const uint4*)(pW4 + (kc * 2 + nc) * 128 * 136);
                uint4* sdst = (uint4*)sW;
                for (int i = t; i < 128 * 136 / 8; i += 256) sdst[i] = gsrc[i];
            }
            if (kc == 0 && t < 128) sb[t] = b4[nc * 128 + t];
            __syncthreads();

#pragma unroll
            for (int kt = 0; kt < 8; kt++) {
                wmma::fragment<wmma::matrix_a, 16, 16, 16, __half, wmma::row_major> a;
                wmma::load_matrix_sync(a, sIn + w * 16 * 136 + kt * 16, 136);
#pragma unroll
                for (int nt = 0; nt < 8; nt++) {
                    wmma::fragment<wmma::matrix_b, 16, 16, 16, __half, wmma::row_major> b;
                    wmma::load_matrix_sync(b, sW + kt * 16 * 136 + nt * 16, 136);
                    wmma::mma_sync(acc[nt], a, b, acc[nt]);
                }
            }
        }

#pragma unroll
        for (int nt = 0; nt < 8; nt++) {
            wmma::store_matrix_sync(wb, acc[nt], 16, wmma::mem_row_major);
            __syncwarp();
            const int cc = nt * 16 + c4;
            const float4 bias = *reinterpret_cast<const float4*>(sb + cc);
#pragma unroll
            for (int h = 0; h < 16; h += 8) {
                const int node = n0 + w * 16 + erow + h;
                if (node < NN) {
                    float4 v = *reinterpret_cast<const float4*>(wb + (erow + h) * 16 + c4);
                    v = relu4_add(v, bias);
                    *reinterpret_cast<float4*>(out + (size_t)node * 256 + nc * 128 + cc) = v;
                }
            }
            __syncwarp();
        }
    }
}

// ---------------------------------------------------------------------------
extern "C" void kernel_launch(void* const* d_in, const int* in_sizes, int n_in,
                              void* d_out, int out_size)
{
    const float* x  = (const float*)d_in[0];
    const void*  ei = d_in[1];
    const float* ea = (const float*)d_in[2];
    const float* W1 = (const float*)d_in[3];
    const float* b1 = (const float*)d_in[4];
    const float* W2 = (const float*)d_in[5];
    const float* b2 = (const float*)d_in[6];
    const float* W3 = (const float*)d_in[7];
    const float* b3 = (const float*)d_in[8];
    const float* W4 = (const float*)d_in[9];
    const float* b4 = (const float*)d_in[10];
    float* out = (float*)d_out;

    cudaFuncSetAttribute(edge_kernel,
                         cudaFuncAttributeMaxDynamicSharedMemorySize, EDGE_SMEM);
    cudaFuncSetAttribute(node1_kernel,
                         cudaFuncAttributeMaxDynamicSharedMemorySize, NODE1_SMEM);
    cudaFuncSetAttribute(node2_kernel,
                         cudaFuncAttributeMaxDynamicSharedMemorySize, NODE2_SMEM);

    detect_kernel<<<1, 32>>>((const long long*)ei);
    prep_kernel<<<64, 256>>>(W1, W2, W3, W4);
    zero_kernel<<<2048, 256>>>();
    edge_kernel<<<NE / 256, 256, EDGE_SMEM>>>(x, ei, ea, b1, b2);
    node1_kernel<<<(NN + 127) / 128, 256, NODE1_SMEM>>>(x, b3);
    node2_kernel<<<(NN + 127) / 128, 256, NODE2_SMEM>>>(b4, out);
}